// round 4
// baseline (speedup 1.0000x reference)
#include <cuda_runtime.h>
#include <math.h>

// ChebyshevDescriptor — thread-per-atom layout.
// N=20000 atoms, K=24 neighbors, output [N,52] = [rad_un17 | rad_w17 | ang_un9 | ang_w9].
//
// Each thread owns one atom: gathers its 24 neighbors, accumulates all 34
// radial sums in registers, stages per-neighbor (ux,uy,uz,ws) as a private
// COLUMN of a lane-major shared array (conflict-free LDS.128), then walks all
// 276 (j<k) pairs accumulating 18 angular sums in registers. No shuffles, no
// barriers, no cross-lane reduction — outputs stored directly (vectorized).

#define N_ATOMS   20000
#define KNBR      24
#define RAD_CUT   8.0f
#define ANG_CUT   6.5f
#define MIN_CUT   0.55f
#define BT        96          // threads per block; smem = 24*96*16 = 36.9 KB

__global__ __launch_bounds__(BT)
void cheb_desc_kernel(const float* __restrict__ pos,
                      const int* __restrict__ spec,
                      const int* __restrict__ nbr,
                      float* __restrict__ out) {
    __shared__ float4 s_u4[KNBR][BT];   // [neighbor][thread] — lane-major columns

    const int t = threadIdx.x;
    const int atom = blockIdx.x * BT + t;
    if (atom >= N_ATOMS) return;        // no barriers below, safe to exit

    const float px = pos[3 * atom + 0];
    const float py = pos[3 * atom + 1];
    const float pz = pos[3 * atom + 2];

    // ---------------- pass 1: gather + radial accumulate ----------------
    float ru[17], rw[17];
    #pragma unroll
    for (int q = 0; q < 17; q++) { ru[q] = 0.0f; rw[q] = 0.0f; }

    const int4* nb4 = (const int4*)(nbr + atom * KNBR);   // atom*96B, 16B-aligned

    #pragma unroll 1
    for (int g = 0; g < 6; g++) {
        const int4 nb = nb4[g];
        #pragma unroll
        for (int jj = 0; jj < 4; jj++) {
            const int j = (jj == 0) ? nb.x : (jj == 1) ? nb.y : (jj == 2) ? nb.z : nb.w;
            const float dx = pos[3 * j + 0] - px;
            const float dy = pos[3 * j + 1] - py;
            const float dz = pos[3 * j + 2] - pz;
            const float d2 = dx * dx + dy * dy + dz * dz;
            const float inv = rsqrtf(fmaxf(d2, 1e-18f));
            const float d = d2 * inv;
            const float sj = (spec[j] != 0) ? 1.0f : -1.0f;   // TYPESPIN = [-1, 1]

            const bool mr = (d <= RAD_CUT) && (d > MIN_CUT);
            const float fc = 0.5f * (cospif(d * (1.0f / RAD_CUT)) + 1.0f);
            const float wr  = mr ? fc : 0.0f;
            const float wrs = wr * sj;
            const float x = mr ? (2.0f * (d - MIN_CUT) * (1.0f / (RAD_CUT - MIN_CUT)) - 1.0f)
                               : 0.0f;   // keep recurrence bounded when masked

            const bool ma = (d <= ANG_CUT) && (d > MIN_CUT);
            const float fca = 0.5f * (cospif(d * (1.0f / ANG_CUT)) + 1.0f);
            const float wa = ma ? fca : 0.0f;

            s_u4[g * 4 + jj][t] = make_float4(dx * inv, dy * inv, dz * inv, wa * sj);

            ru[0] += wr;        rw[0] += wrs;
            ru[1] += wr * x;    rw[1] += wrs * x;
            const float x2 = x + x;
            float Tmm = 1.0f, Tm = x;
            #pragma unroll
            for (int q = 2; q < 17; q++) {
                const float T = x2 * Tm - Tmm;
                ru[q] += wr * T;
                rw[q] += wrs * T;
                Tmm = Tm; Tm = T;
            }
        }
    }

    // radial outputs: out[0..16] = ru, out[17..33] = rw  (vectorized stores)
    float* o = out + (size_t)atom * 52;   // 208B-aligned (208 = 16*13)
    #pragma unroll
    for (int q = 0; q < 4; q++)
        ((float4*)o)[q] = make_float4(ru[4 * q], ru[4 * q + 1], ru[4 * q + 2], ru[4 * q + 3]);
    ((float2*)o)[8] = make_float2(ru[16], rw[0]);            // out[16], out[17]
    #pragma unroll
    for (int q = 0; q < 8; q++)
        ((float2*)(o + 18))[q] = make_float2(rw[1 + 2 * q], rw[2 + 2 * q]);  // out[18..33]

    // ---------------- pass 2: angular over 276 (j<k) pairs ----------------
    float aU[9], aW[9];
    #pragma unroll
    for (int q = 0; q < 9; q++) { aU[q] = 0.0f; aW[q] = 0.0f; }

    const float4* col = &s_u4[0][t];     // this thread's column, stride BT float4s

    #pragma unroll 1
    for (int jj = 0; jj < KNBR - 1; jj++) {
        const float4 a = col[jj * BT];
        float4 b = col[(jj + 1) * BT];
        #pragma unroll 1
        for (int kk = jj + 1; kk < KNBR; kk++) {
            const int kn = (kk + 1 < KNBR) ? (kk + 1) : (KNBR - 1);
            const float4 bn = col[kn * BT];          // prefetch next partner

            float ct = a.x * b.x + a.y * b.y + a.z * b.z;
            ct = fminf(fmaxf(ct, -1.0f), 1.0f);
            const float wsp = a.w * b.w;             // (wa_j sj)(wa_k sk)
            const float wp  = fabsf(wsp);            // wa_j wa_k

            aU[0] += wp;        aW[0] += wsp;
            aU[1] += wp * ct;   aW[1] += wsp * ct;
            const float c2 = ct + ct;
            float Tmm = 1.0f, Tm = ct;
            #pragma unroll
            for (int q = 2; q < 9; q++) {
                const float T = c2 * Tm - Tmm;
                aU[q] += wp * T;
                aW[q] += wsp * T;
                Tmm = Tm; Tm = T;
            }
            b = bn;
        }
    }

    // angular outputs: out[34..42] = aU, out[43..51] = aW
    #pragma unroll
    for (int q = 0; q < 4; q++)
        ((float2*)(o + 34))[q] = make_float2(aU[2 * q], aU[2 * q + 1]);      // out[34..41]
    ((float2*)(o + 42))[0] = make_float2(aU[8], aW[0]);                      // out[42], out[43]
    #pragma unroll
    for (int q = 0; q < 4; q++)
        ((float2*)(o + 44))[q] = make_float2(aW[1 + 2 * q], aW[2 + 2 * q]);  // out[44..51]
}

extern "C" void kernel_launch(void* const* d_in, const int* in_sizes, int n_in,
                              void* d_out, int out_size) {
    const float* positions  = (const float*)d_in[0];
    const int* species_idx  = (const int*)d_in[1];
    const int* neighbor_idx = (const int*)d_in[2];
    float* out = (float*)d_out;

    const int blocks = (N_ATOMS + BT - 1) / BT;   // 209
    cheb_desc_kernel<<<blocks, BT>>>(positions, species_idx, neighbor_idx, out);
}

// round 5
// speedup vs baseline: 1.6368x; 1.6368x over previous
#include <cuda_runtime.h>
#include <math.h>

// ChebyshevDescriptor — 4 threads per atom (quad), 80000 threads total.
// N=20000 atoms, K=24 neighbors, out [N,52] = [rad_un17 | rad_w17 | ang_un9 | ang_w9].
//
// Subthread s (0..3) of an atom owns neighbors j = s+4m, m=0..5: gathers them,
// accumulates radial partials, keeps (ux,uy,uz,ws) in registers AND stages
// them to a per-atom shared table. Angular pairs enumerated by rotation:
// (j, (j+r) mod 24), r=1..11 all j, r=12 for j<12 -> exactly 69 pairs per
// subthread, own side from registers, partner via one LDS.128. Quad sums
// merged with 2 butterfly shuffles per value; lane s==0 stores vectorized.

#define N_ATOMS 20000
#define KNBR    24
#define RAD_CUT 8.0f
#define ANG_CUT 6.5f
#define MIN_CUT 0.55f
#define BT      64
#define APB     (BT / 4)     // 16 atoms per block
#define SSTR    25           // padded float4 stride: breaks cross-atom bank conflicts

__global__ __launch_bounds__(BT)
void cheb_desc_kernel(const float* __restrict__ pos,
                      const int* __restrict__ spec,
                      const int* __restrict__ nbr,
                      float* __restrict__ out) {
    __shared__ float4 s_u4[APB][SSTR];   // 16*25*16B = 6.4 KB

    const int t = threadIdx.x;
    const int s = t & 3;                 // subthread within quad
    const int a = t >> 2;                // atom within block
    const int atom = blockIdx.x * APB + a;   // grid 1250 * 16 == 20000 exactly

    const float px = pos[3 * atom + 0];
    const float py = pos[3 * atom + 1];
    const float pz = pos[3 * atom + 2];

    // ---------------- pass 1: gather own 6 neighbors + radial partials ----------------
    float ru[17], rw[17];
    #pragma unroll
    for (int q = 0; q < 17; q++) { ru[q] = 0.0f; rw[q] = 0.0f; }

    float4 myu[6];

    #pragma unroll
    for (int m = 0; m < 6; m++) {
        const int j = s + 4 * m;
        const int nj = nbr[atom * KNBR + j];
        const float dx = pos[3 * nj + 0] - px;
        const float dy = pos[3 * nj + 1] - py;
        const float dz = pos[3 * nj + 2] - pz;
        const float d2 = dx * dx + dy * dy + dz * dz;
        const float inv = rsqrtf(fmaxf(d2, 1e-18f));
        const float d = d2 * inv;
        const float sj = (spec[nj] != 0) ? 1.0f : -1.0f;   // TYPESPIN = [-1, 1]

        const bool mr = (d <= RAD_CUT) && (d > MIN_CUT);
        const float fc = 0.5f * (cospif(d * (1.0f / RAD_CUT)) + 1.0f);
        const float wr  = mr ? fc : 0.0f;
        const float wrs = wr * sj;
        const float x = mr ? (2.0f * (d - MIN_CUT) * (1.0f / (RAD_CUT - MIN_CUT)) - 1.0f)
                           : 0.0f;   // weight is 0 when masked; x=0 keeps T bounded

        const bool ma = (d <= ANG_CUT) && (d > MIN_CUT);
        const float fca = 0.5f * (cospif(d * (1.0f / ANG_CUT)) + 1.0f);
        const float wa = ma ? fca : 0.0f;

        const float4 u = make_float4(dx * inv, dy * inv, dz * inv, wa * sj);
        myu[m] = u;
        s_u4[a][j] = u;

        ru[0] += wr;        rw[0] += wrs;
        ru[1] += wr * x;    rw[1] += wrs * x;
        const float x2 = x + x;
        float Tmm = 1.0f, Tm = x;
        #pragma unroll
        for (int q = 2; q < 17; q++) {
            const float T = x2 * Tm - Tmm;
            ru[q] += wr * T;
            rw[q] += wrs * T;
            Tmm = Tm; Tm = T;
        }
    }

    // quad-reduce radial (lanes of a quad differ only in bits 0..1)
    #pragma unroll
    for (int q = 0; q < 17; q++) {
        ru[q] += __shfl_xor_sync(0xffffffffu, ru[q], 1);
        ru[q] += __shfl_xor_sync(0xffffffffu, ru[q], 2);
        rw[q] += __shfl_xor_sync(0xffffffffu, rw[q], 1);
        rw[q] += __shfl_xor_sync(0xffffffffu, rw[q], 2);
    }

    float* o = out + (size_t)atom * 52;   // 208B = 16*13 -> 16B-aligned
    if (s == 0) {
        ((float4*)o)[0] = make_float4(ru[0],  ru[1],  ru[2],  ru[3]);
        ((float4*)o)[1] = make_float4(ru[4],  ru[5],  ru[6],  ru[7]);
        ((float4*)o)[2] = make_float4(ru[8],  ru[9],  ru[10], ru[11]);
        ((float4*)o)[3] = make_float4(ru[12], ru[13], ru[14], ru[15]);
        ((float4*)o)[4] = make_float4(ru[16], rw[0],  rw[1],  rw[2]);
        ((float4*)o)[5] = make_float4(rw[3],  rw[4],  rw[5],  rw[6]);
        ((float4*)o)[6] = make_float4(rw[7],  rw[8],  rw[9],  rw[10]);
        ((float4*)o)[7] = make_float4(rw[11], rw[12], rw[13], rw[14]);
        ((float2*)o)[16] = make_float2(rw[15], rw[16]);   // out[32..33]
    }

    __syncwarp();   // staging visible to quad partners (same warp)

    // ---------------- pass 2: angular, rotation pairs, 69 per subthread ----------------
    float aU[9], aW[9];
    #pragma unroll
    for (int q = 0; q < 9; q++) { aU[q] = 0.0f; aW[q] = 0.0f; }

    #pragma unroll 1
    for (int r = 1; r <= 11; r++) {
        const int kb = s + r;
        #pragma unroll
        for (int m = 0; m < 6; m++) {
            int k = kb + 4 * m;
            if (k >= KNBR) k -= KNBR;
            const float4 av = myu[m];
            const float4 b = s_u4[a][k];

            const float wsp = av.w * b.w;
            const float wp  = fabsf(wsp);
            float ct = av.x * b.x + av.y * b.y + av.z * b.z;
            ct = fminf(fmaxf(ct, -1.0f), 1.0f);

            aU[0] += wp;        aW[0] += wsp;
            aU[1] += wp * ct;   aW[1] += wsp * ct;
            const float c2 = ct + ct;
            float Tmm = 1.0f, Tm = ct;
            #pragma unroll
            for (int q = 2; q < 9; q++) {
                const float T = c2 * Tm - Tmm;
                aU[q] += wp * T;
                aW[q] += wsp * T;
                Tmm = Tm; Tm = T;
            }
        }
    }
    {   // r = 12: only j = s+4m < 12 -> m = 0..2 for every s
        const int kb = s + 12;
        #pragma unroll
        for (int m = 0; m < 3; m++) {
            int k = kb + 4 * m;
            if (k >= KNBR) k -= KNBR;
            const float4 av = myu[m];
            const float4 b = s_u4[a][k];

            const float wsp = av.w * b.w;
            const float wp  = fabsf(wsp);
            float ct = av.x * b.x + av.y * b.y + av.z * b.z;
            ct = fminf(fmaxf(ct, -1.0f), 1.0f);

            aU[0] += wp;        aW[0] += wsp;
            aU[1] += wp * ct;   aW[1] += wsp * ct;
            const float c2 = ct + ct;
            float Tmm = 1.0f, Tm = ct;
            #pragma unroll
            for (int q = 2; q < 9; q++) {
                const float T = c2 * Tm - Tmm;
                aU[q] += wp * T;
                aW[q] += wsp * T;
                Tmm = Tm; Tm = T;
            }
        }
    }

    // quad-reduce angular
    #pragma unroll
    for (int q = 0; q < 9; q++) {
        aU[q] += __shfl_xor_sync(0xffffffffu, aU[q], 1);
        aU[q] += __shfl_xor_sync(0xffffffffu, aU[q], 2);
        aW[q] += __shfl_xor_sync(0xffffffffu, aW[q], 1);
        aW[q] += __shfl_xor_sync(0xffffffffu, aW[q], 2);
    }

    if (s == 0) {   // out[34..51], base 8B-aligned -> float2 stores
        float2* o2 = (float2*)(o + 34);
        o2[0] = make_float2(aU[0], aU[1]);
        o2[1] = make_float2(aU[2], aU[3]);
        o2[2] = make_float2(aU[4], aU[5]);
        o2[3] = make_float2(aU[6], aU[7]);
        o2[4] = make_float2(aU[8], aW[0]);
        o2[5] = make_float2(aW[1], aW[2]);
        o2[6] = make_float2(aW[3], aW[4]);
        o2[7] = make_float2(aW[5], aW[6]);
        o2[8] = make_float2(aW[7], aW[8]);
    }
}

extern "C" void kernel_launch(void* const* d_in, const int* in_sizes, int n_in,
                              void* d_out, int out_size) {
    const float* positions  = (const float*)d_in[0];
    const int* species_idx  = (const int*)d_in[1];
    const int* neighbor_idx = (const int*)d_in[2];
    float* out = (float*)d_out;

    const int blocks = N_ATOMS / APB;   // 1250, exact
    cheb_desc_kernel<<<blocks, BT>>>(positions, species_idx, neighbor_idx, out);
}

// round 8
// speedup vs baseline: 1.6950x; 1.0356x over previous
#include <cuda_runtime.h>
#include <math.h>

// ChebyshevDescriptor — 8 threads per atom, scalar f32 math.
// N=20000, K=24, out [N,52] = [rad_un17 | rad_w17 | ang_un9 | ang_w9].
//
// kernel 1 packs positions+typespin into a float4 table (1 LDG.128 per
// neighbor gather). kernel 2: subthread s (0..7) of an atom owns neighbors
// j = s+8m (m=0..2): gathers them, radial partials in registers, stages
// (ux,uy,uz,ws) to a per-atom shared float4 table and keeps them in regs.
// Angular pairs by rotation (j, (j+r) mod 24): r=1..11 for all owned j,
// r=12 for owned j<12 -> 34-35 pairs/thread, 276 total. Octet reduction =
// 3 butterfly shuffles (lanes of an atom differ in bits 0..2). Lane s==0
// stores vectorized. No exotic PTX (prior f32x2 build failed the container).

#define N_ATOMS 20000
#define KNBR    24
#define RAD_CUT 8.0f
#define ANG_CUT 6.5f
#define MIN_CUT 0.55f
#define BT      64
#define APB     8            // atoms per block
#define SSTR    25           // padded float4 stride

__device__ float4 g_pos4[N_ATOMS];   // (x, y, z, typespin)

__global__ void pack_kernel(const float* __restrict__ pos, const int* __restrict__ spec) {
    const int i = blockIdx.x * blockDim.x + threadIdx.x;
    if (i < N_ATOMS)
        g_pos4[i] = make_float4(pos[3 * i], pos[3 * i + 1], pos[3 * i + 2],
                                spec[i] ? 1.0f : -1.0f);
}

__global__ __launch_bounds__(BT)
void cheb_kernel(const int* __restrict__ nbr, float* __restrict__ out) {
    __shared__ float4 s_u4[APB][SSTR];    // 8*25*16B = 3.2 KB

    const int t = threadIdx.x;
    const int s = t & 7;                  // subthread within octet
    const int a = t >> 3;                 // atom within block
    const int atom = blockIdx.x * APB + a;    // 2500 * 8 == 20000 exactly

    const float4 me = g_pos4[atom];

    // ---------------- pass 1: gather own 3 neighbors + radial partials ----------------
    float ru[17], rw[17];
    #pragma unroll
    for (int q = 0; q < 17; q++) { ru[q] = 0.0f; rw[q] = 0.0f; }

    float4 myu[3];

    #pragma unroll
    for (int m = 0; m < 3; m++) {
        const int j = s + 8 * m;
        const int nj = nbr[atom * KNBR + j];
        const float4 p = g_pos4[nj];
        const float dx = p.x - me.x, dy = p.y - me.y, dz = p.z - me.z;
        const float d2 = dx * dx + dy * dy + dz * dz;
        const float inv = rsqrtf(fmaxf(d2, 1e-18f));
        const float d = d2 * inv;
        const float sj = p.w;

        const bool mr = (d <= RAD_CUT) && (d > MIN_CUT);
        const float fc = 0.5f * (__cosf(d * (3.14159265358979f / RAD_CUT)) + 1.0f);
        const float wr  = mr ? fc : 0.0f;
        const float wrs = wr * sj;
        const float x = mr ? (2.0f * (d - MIN_CUT) * (1.0f / (RAD_CUT - MIN_CUT)) - 1.0f)
                           : 0.0f;   // weight 0 when masked; x=0 keeps T bounded

        const bool ma = (d <= ANG_CUT) && (d > MIN_CUT);
        const float fca = 0.5f * (__cosf(d * (3.14159265358979f / ANG_CUT)) + 1.0f);
        const float wa = ma ? fca : 0.0f;

        const float4 u = make_float4(dx * inv, dy * inv, dz * inv, wa * sj);
        myu[m] = u;
        s_u4[a][j] = u;

        ru[0] += wr;        rw[0] += wrs;
        ru[1] += wr * x;    rw[1] += wrs * x;
        const float x2 = x + x;
        float Tmm = 1.0f, Tm = x;
        #pragma unroll
        for (int q = 2; q < 17; q++) {
            const float T = x2 * Tm - Tmm;
            ru[q] += wr * T;
            rw[q] += wrs * T;
            Tmm = Tm; Tm = T;
        }
    }

    // octet-reduce radial (lanes of an atom differ in bits 0..2)
    #pragma unroll
    for (int q = 0; q < 17; q++) {
        ru[q] += __shfl_xor_sync(0xffffffffu, ru[q], 1);
        ru[q] += __shfl_xor_sync(0xffffffffu, ru[q], 2);
        ru[q] += __shfl_xor_sync(0xffffffffu, ru[q], 4);
        rw[q] += __shfl_xor_sync(0xffffffffu, rw[q], 1);
        rw[q] += __shfl_xor_sync(0xffffffffu, rw[q], 2);
        rw[q] += __shfl_xor_sync(0xffffffffu, rw[q], 4);
    }

    float* o = out + (size_t)atom * 52;   // 208B = 16*13 -> 16B-aligned
    if (s == 0) {
        ((float4*)o)[0] = make_float4(ru[0],  ru[1],  ru[2],  ru[3]);
        ((float4*)o)[1] = make_float4(ru[4],  ru[5],  ru[6],  ru[7]);
        ((float4*)o)[2] = make_float4(ru[8],  ru[9],  ru[10], ru[11]);
        ((float4*)o)[3] = make_float4(ru[12], ru[13], ru[14], ru[15]);
        ((float4*)o)[4] = make_float4(ru[16], rw[0],  rw[1],  rw[2]);
        ((float4*)o)[5] = make_float4(rw[3],  rw[4],  rw[5],  rw[6]);
        ((float4*)o)[6] = make_float4(rw[7],  rw[8],  rw[9],  rw[10]);
        ((float4*)o)[7] = make_float4(rw[11], rw[12], rw[13], rw[14]);
        ((float2*)o)[16] = make_float2(rw[15], rw[16]);   // out[32..33]
    }

    __syncwarp();   // staging visible: octet spans lanes of one warp only

    // ---------------- pass 2: angular, rotation pairs ----------------
    float aU[9], aW[9];
    #pragma unroll
    for (int q = 0; q < 9; q++) { aU[q] = 0.0f; aW[q] = 0.0f; }

    #pragma unroll 1
    for (int r = 1; r <= 11; r++) {
        const int kb = s + r;
        #pragma unroll
        for (int m = 0; m < 3; m++) {
            int k = kb + 8 * m;
            if (k >= KNBR) k -= KNBR;
            const float4 av = myu[m];
            const float4 b = s_u4[a][k];

            const float wsp = av.w * b.w;     // (wa_j sj)(wa_k sk)
            const float wp  = fabsf(wsp);     // wa_j wa_k
            float ct = av.x * b.x + av.y * b.y + av.z * b.z;
            ct = fminf(fmaxf(ct, -1.0f), 1.0f);

            aU[0] += wp;        aW[0] += wsp;
            aU[1] += wp * ct;   aW[1] += wsp * ct;
            const float c2 = ct + ct;
            float Tmm = 1.0f, Tm = ct;
            #pragma unroll
            for (int q = 2; q < 9; q++) {
                const float T = c2 * Tm - Tmm;
                aU[q] += wp * T;
                aW[q] += wsp * T;
                Tmm = Tm; Tm = T;
            }
        }
    }
    {   // r = 12: owned j = s+8m < 12  ->  m <= 1 for s < 4, m == 0 for s >= 4
        const int mmax = (s < 4) ? 2 : 1;
        #pragma unroll 1
        for (int m = 0; m < mmax; m++) {
            int k = s + 12 + 8 * m;
            if (k >= KNBR) k -= KNBR;
            const float4 av = myu[m];
            const float4 b = s_u4[a][k];

            const float wsp = av.w * b.w;
            const float wp  = fabsf(wsp);
            float ct = av.x * b.x + av.y * b.y + av.z * b.z;
            ct = fminf(fmaxf(ct, -1.0f), 1.0f);

            aU[0] += wp;        aW[0] += wsp;
            aU[1] += wp * ct;   aW[1] += wsp * ct;
            const float c2 = ct + ct;
            float Tmm = 1.0f, Tm = ct;
            #pragma unroll
            for (int q = 2; q < 9; q++) {
                const float T = c2 * Tm - Tmm;
                aU[q] += wp * T;
                aW[q] += wsp * T;
                Tmm = Tm; Tm = T;
            }
        }
    }

    // octet-reduce angular
    #pragma unroll
    for (int q = 0; q < 9; q++) {
        aU[q] += __shfl_xor_sync(0xffffffffu, aU[q], 1);
        aU[q] += __shfl_xor_sync(0xffffffffu, aU[q], 2);
        aU[q] += __shfl_xor_sync(0xffffffffu, aU[q], 4);
        aW[q] += __shfl_xor_sync(0xffffffffu, aW[q], 1);
        aW[q] += __shfl_xor_sync(0xffffffffu, aW[q], 2);
        aW[q] += __shfl_xor_sync(0xffffffffu, aW[q], 4);
    }

    if (s == 0) {   // out[34..51], 8B-aligned base -> float2 stores
        float2* o2 = (float2*)(o + 34);
        o2[0] = make_float2(aU[0], aU[1]);
        o2[1] = make_float2(aU[2], aU[3]);
        o2[2] = make_float2(aU[4], aU[5]);
        o2[3] = make_float2(aU[6], aU[7]);
        o2[4] = make_float2(aU[8], aW[0]);
        o2[5] = make_float2(aW[1], aW[2]);
        o2[6] = make_float2(aW[3], aW[4]);
        o2[7] = make_float2(aW[5], aW[6]);
        o2[8] = make_float2(aW[7], aW[8]);
    }
}

extern "C" void kernel_launch(void* const* d_in, const int* in_sizes, int n_in,
                              void* d_out, int out_size) {
    const float* positions  = (const float*)d_in[0];
    const int* species_idx  = (const int*)d_in[1];
    const int* neighbor_idx = (const int*)d_in[2];
    float* out = (float*)d_out;

    pack_kernel<<<(N_ATOMS + 255) / 256, 256>>>(positions, species_idx);
    cheb_kernel<<<N_ATOMS / APB, BT>>>(neighbor_idx, out);   // 2500 blocks
}

// round 9
// speedup vs baseline: 1.7083x; 1.0078x over previous
#include <cuda_runtime.h>
#include <math.h>

// ChebyshevDescriptor — 8 threads per atom, scalar f32 math.
// N=20000, K=24, out [N,52] = [rad_un17 | rad_w17 | ang_un9 | ang_w9].
//
// R8 deltas vs R7: __launch_bounds__(64,17) caps regs at 60 so all 2500
// blocks are resident in a single wave (was 16 blocks/SM -> 2-wave tail);
// dropped the cos-theta clamp (|ct|<=1+ulp, harmless at 1e-3 tolerance);
// pointer-increment partner addressing in the rotation loop.

#define N_ATOMS 20000
#define KNBR    24
#define RAD_CUT 8.0f
#define ANG_CUT 6.5f
#define MIN_CUT 0.55f
#define BT      64
#define APB     8            // atoms per block
#define SSTR    25           // padded float4 stride

__device__ float4 g_pos4[N_ATOMS];   // (x, y, z, typespin)

__global__ void pack_kernel(const float* __restrict__ pos, const int* __restrict__ spec) {
    const int i = blockIdx.x * blockDim.x + threadIdx.x;
    if (i < N_ATOMS)
        g_pos4[i] = make_float4(pos[3 * i], pos[3 * i + 1], pos[3 * i + 2],
                                spec[i] ? 1.0f : -1.0f);
}

__global__ __launch_bounds__(BT, 17)
void cheb_kernel(const int* __restrict__ nbr, float* __restrict__ out) {
    __shared__ float4 s_u4[APB][SSTR];    // 8*25*16B = 3.2 KB

    const int t = threadIdx.x;
    const int s = t & 7;                  // subthread within octet
    const int a = t >> 3;                 // atom within block
    const int atom = blockIdx.x * APB + a;    // 2500 * 8 == 20000 exactly

    const float4 me = g_pos4[atom];

    // ---------------- pass 1: gather own 3 neighbors + radial partials ----------------
    float ru[17], rw[17];
    #pragma unroll
    for (int q = 0; q < 17; q++) { ru[q] = 0.0f; rw[q] = 0.0f; }

    float4 myu[3];

    #pragma unroll
    for (int m = 0; m < 3; m++) {
        const int j = s + 8 * m;
        const int nj = nbr[atom * KNBR + j];
        const float4 p = g_pos4[nj];
        const float dx = p.x - me.x, dy = p.y - me.y, dz = p.z - me.z;
        const float d2 = dx * dx + dy * dy + dz * dz;
        const float inv = rsqrtf(fmaxf(d2, 1e-18f));
        const float d = d2 * inv;
        const float sj = p.w;

        const bool mr = (d <= RAD_CUT) && (d > MIN_CUT);
        const float fc = 0.5f * (__cosf(d * (3.14159265358979f / RAD_CUT)) + 1.0f);
        const float wr  = mr ? fc : 0.0f;
        const float wrs = wr * sj;
        const float x = mr ? (2.0f * (d - MIN_CUT) * (1.0f / (RAD_CUT - MIN_CUT)) - 1.0f)
                           : 0.0f;   // weight 0 when masked; x=0 keeps T bounded

        const bool ma = (d <= ANG_CUT) && (d > MIN_CUT);
        const float fca = 0.5f * (__cosf(d * (3.14159265358979f / ANG_CUT)) + 1.0f);
        const float wa = ma ? fca : 0.0f;

        const float4 u = make_float4(dx * inv, dy * inv, dz * inv, wa * sj);
        myu[m] = u;
        s_u4[a][j] = u;

        ru[0] += wr;        rw[0] += wrs;
        ru[1] += wr * x;    rw[1] += wrs * x;
        const float x2 = x + x;
        float Tmm = 1.0f, Tm = x;
        #pragma unroll
        for (int q = 2; q < 17; q++) {
            const float T = x2 * Tm - Tmm;
            ru[q] += wr * T;
            rw[q] += wrs * T;
            Tmm = Tm; Tm = T;
        }
    }

    // octet-reduce radial (lanes of an atom differ in bits 0..2)
    #pragma unroll
    for (int q = 0; q < 17; q++) {
        ru[q] += __shfl_xor_sync(0xffffffffu, ru[q], 1);
        ru[q] += __shfl_xor_sync(0xffffffffu, ru[q], 2);
        ru[q] += __shfl_xor_sync(0xffffffffu, ru[q], 4);
        rw[q] += __shfl_xor_sync(0xffffffffu, rw[q], 1);
        rw[q] += __shfl_xor_sync(0xffffffffu, rw[q], 2);
        rw[q] += __shfl_xor_sync(0xffffffffu, rw[q], 4);
    }

    float* o = out + (size_t)atom * 52;   // 208B = 16*13 -> 16B-aligned
    if (s == 0) {
        ((float4*)o)[0] = make_float4(ru[0],  ru[1],  ru[2],  ru[3]);
        ((float4*)o)[1] = make_float4(ru[4],  ru[5],  ru[6],  ru[7]);
        ((float4*)o)[2] = make_float4(ru[8],  ru[9],  ru[10], ru[11]);
        ((float4*)o)[3] = make_float4(ru[12], ru[13], ru[14], ru[15]);
        ((float4*)o)[4] = make_float4(ru[16], rw[0],  rw[1],  rw[2]);
        ((float4*)o)[5] = make_float4(rw[3],  rw[4],  rw[5],  rw[6]);
        ((float4*)o)[6] = make_float4(rw[7],  rw[8],  rw[9],  rw[10]);
        ((float4*)o)[7] = make_float4(rw[11], rw[12], rw[13], rw[14]);
        ((float2*)o)[16] = make_float2(rw[15], rw[16]);   // out[32..33]
    }

    __syncwarp();   // staging visible: octet spans lanes of one warp only

    // ---------------- pass 2: angular, rotation pairs ----------------
    float aU[9], aW[9];
    #pragma unroll
    for (int q = 0; q < 9; q++) { aU[q] = 0.0f; aW[q] = 0.0f; }

    const float4* srow = &s_u4[a][0];

    #pragma unroll 1
    for (int r = 1; r <= 11; r++) {
        int k0 = s + r;                       // partner index for m=0 (may wrap)
        #pragma unroll
        for (int m = 0; m < 3; m++) {
            int k = k0 + 8 * m;
            if (k >= KNBR) k -= KNBR;
            const float4 av = myu[m];
            const float4 b = srow[k];

            const float wsp = av.w * b.w;     // (wa_j sj)(wa_k sk)
            const float wp  = fabsf(wsp);     // wa_j wa_k
            const float ct = av.x * b.x + av.y * b.y + av.z * b.z;   // |ct|<=1+ulp

            aU[0] += wp;        aW[0] += wsp;
            aU[1] += wp * ct;   aW[1] += wsp * ct;
            const float c2 = ct + ct;
            float Tmm = 1.0f, Tm = ct;
            #pragma unroll
            for (int q = 2; q < 9; q++) {
                const float T = c2 * Tm - Tmm;
                aU[q] += wp * T;
                aW[q] += wsp * T;
                Tmm = Tm; Tm = T;
            }
        }
    }
    {   // r = 12: owned j = s+8m < 12  ->  m <= 1 for s < 4, m == 0 for s >= 4
        const int mmax = (s < 4) ? 2 : 1;
        #pragma unroll 1
        for (int m = 0; m < mmax; m++) {
            int k = s + 12 + 8 * m;
            if (k >= KNBR) k -= KNBR;
            const float4 av = myu[m];
            const float4 b = srow[k];

            const float wsp = av.w * b.w;
            const float wp  = fabsf(wsp);
            const float ct = av.x * b.x + av.y * b.y + av.z * b.z;

            aU[0] += wp;        aW[0] += wsp;
            aU[1] += wp * ct;   aW[1] += wsp * ct;
            const float c2 = ct + ct;
            float Tmm = 1.0f, Tm = ct;
            #pragma unroll
            for (int q = 2; q < 9; q++) {
                const float T = c2 * Tm - Tmm;
                aU[q] += wp * T;
                aW[q] += wsp * T;
                Tmm = Tm; Tm = T;
            }
        }
    }

    // octet-reduce angular
    #pragma unroll
    for (int q = 0; q < 9; q++) {
        aU[q] += __shfl_xor_sync(0xffffffffu, aU[q], 1);
        aU[q] += __shfl_xor_sync(0xffffffffu, aU[q], 2);
        aU[q] += __shfl_xor_sync(0xffffffffu, aU[q], 4);
        aW[q] += __shfl_xor_sync(0xffffffffu, aW[q], 1);
        aW[q] += __shfl_xor_sync(0xffffffffu, aW[q], 2);
        aW[q] += __shfl_xor_sync(0xffffffffu, aW[q], 4);
    }

    if (s == 0) {   // out[34..51], 8B-aligned base -> float2 stores
        float2* o2 = (float2*)(o + 34);
        o2[0] = make_float2(aU[0], aU[1]);
        o2[1] = make_float2(aU[2], aU[3]);
        o2[2] = make_float2(aU[4], aU[5]);
        o2[3] = make_float2(aU[6], aU[7]);
        o2[4] = make_float2(aU[8], aW[0]);
        o2[5] = make_float2(aW[1], aW[2]);
        o2[6] = make_float2(aW[3], aW[4]);
        o2[7] = make_float2(aW[5], aW[6]);
        o2[8] = make_float2(aW[7], aW[8]);
    }
}

extern "C" void kernel_launch(void* const* d_in, const int* in_sizes, int n_in,
                              void* d_out, int out_size) {
    const float* positions  = (const float*)d_in[0];
    const int* species_idx  = (const int*)d_in[1];
    const int* neighbor_idx = (const int*)d_in[2];
    float* out = (float*)d_out;

    pack_kernel<<<(N_ATOMS + 255) / 256, 256>>>(positions, species_idx);
    cheb_kernel<<<N_ATOMS / APB, BT>>>(neighbor_idx, out);   // 2500 blocks
}